// round 5
// baseline (speedup 1.0000x reference)
#include <cuda_runtime.h>
#include <math.h>
#include <float.h>
#include <stdint.h>

// Problem constants
#define Bv 2
#define Nv 2048
#define Cv 1024
#define Hv 16
#define Dv 64
#define BHv (Bv*Hv)        // 32
#define MROWS (Bv*Nv)      // 4096
#define C3 (3*Cv)          // 3072

// Static device scratch (allocation-free rule)
__device__ float g_q[BHv*Nv*Dv];            // 16 MB, [b,h,n,d]
__device__ float g_k[BHv*Nv*Dv];
__device__ float g_v[BHv*Nv*Dv];
__device__ float g_attn[MROWS*Cv];          // 16 MB, [b*n, h*d]
__device__ int   g_maskflag;

// ---------------- tf32 helpers ----------------
__device__ __forceinline__ float f2tf32(float x) {
    uint32_t u;
    asm("cvt.rna.tf32.f32 %0, %1;" : "=r"(u) : "f"(x));
    return __uint_as_float(u);
}

__device__ __forceinline__ void mma_tf32(float* c, const uint32_t* a, uint32_t b0, uint32_t b1) {
    asm volatile(
        "mma.sync.aligned.m16n8k8.row.col.f32.tf32.tf32.f32 "
        "{%0,%1,%2,%3}, {%4,%5,%6,%7}, {%8,%9}, {%0,%1,%2,%3};\n"
        : "+f"(c[0]), "+f"(c[1]), "+f"(c[2]), "+f"(c[3])
        : "r"(a[0]), "r"(a[1]), "r"(a[2]), "r"(a[3]), "r"(b0), "r"(b1));
}

__device__ __forceinline__ void cp16(uint32_t dst, const void* src) {
    asm volatile("cp.async.cg.shared.global [%0], [%1], 16;\n" :: "r"(dst), "l"(src));
}

// ---------------- Epilogue functors ----------------
struct EpiQKV {
    float *q, *k, *v;
    __device__ __forceinline__ void operator()(int bz, int m, int n, float val) const {
        int b   = m >> 11;
        int tok = m & 2047;
        int which = n >> 10;        // 0=q,1=k,2=v
        int h   = (n & 1023) >> 6;
        int dd  = n & 63;
        if (which == 2) val = f2tf32(val);   // V used directly by attention mma
        float* dst = (which == 0) ? q : ((which == 1) ? k : v);
        dst[(((b*Hv + h)*Nv + tok) << 6) + dd] = val;
    }
};

struct EpiOut {
    float* out;
    const float* bias;
    __device__ __forceinline__ void operator()(int bz, int m, int n, float val) const {
        out[(size_t)m*Cv + n] = val + bias[n];
    }
};

// ============ tf32 tensor-core GEMM, TN, reg-staged double buffer ============
// C = A(MxK,rm) * B(NxK,rm)^T.  BM=BN=128, BK=32, 256 threads.
template<int BM, int BN, int BK, int WM, int WN, class Epi>
__global__ void __launch_bounds__((BM/WM)*(BN/WN)*32)
gemm_tc_tn(const float* __restrict__ A, const float* __restrict__ B,
           int K, long long sA, long long sB, Epi epi)
{
    constexpr int WARPS_M = BM / WM;
    constexpr int WARPS_N = BN / WN;
    constexpr int THREADS = WARPS_M * WARPS_N * 32;
    constexpr int MT = WM / 16;
    constexpr int NT = WN / 8;
    constexpr int PAD = 4;
    constexpr int VPR = BK / 4;                       // 8 float4 per row
    constexpr int CH  = (BM * VPR) / THREADS;         // load chunks (=4)

    __shared__ float As[BM][BK + PAD];
    __shared__ float Bs[BN][BK + PAD];

    const int bz = blockIdx.z;
    A += (long long)bz * sA + (long long)blockIdx.y * BM * K;
    B += (long long)bz * sB + (long long)blockIdx.x * BN * K;
    const int tid  = threadIdx.x;
    const int warp = tid >> 5, lane = tid & 31;
    const int wm = warp / WARPS_N, wn = warp % WARPS_N;
    const int group = lane >> 2, tg = lane & 3;

    float acc[MT][NT][4];
    #pragma unroll
    for (int i = 0; i < MT; i++)
        #pragma unroll
        for (int j = 0; j < NT; j++)
            #pragma unroll
            for (int r = 0; r < 4; r++) acc[i][j][r] = 0.f;

    float4 ra[CH], rb[CH];

    auto load_regs = [&](int k0) {
        #pragma unroll
        for (int j = 0; j < CH; j++) {
            int i = tid + j * THREADS;
            int m = i / VPR, kv = i % VPR;
            ra[j] = *(const float4*)(A + (long long)m * K + k0 + kv * 4);
            rb[j] = *(const float4*)(B + (long long)m * K + k0 + kv * 4);
        }
    };
    auto store_smem = [&]() {
        #pragma unroll
        for (int j = 0; j < CH; j++) {
            int i = tid + j * THREADS;
            int m = i / VPR, kv = i % VPR;
            float4 t = ra[j];
            t.x = f2tf32(t.x); t.y = f2tf32(t.y); t.z = f2tf32(t.z); t.w = f2tf32(t.w);
            *(float4*)&As[m][kv * 4] = t;
            t = rb[j];
            t.x = f2tf32(t.x); t.y = f2tf32(t.y); t.z = f2tf32(t.z); t.w = f2tf32(t.w);
            *(float4*)&Bs[m][kv * 4] = t;
        }
    };

    load_regs(0);
    for (int k0 = 0; k0 < K; k0 += BK) {
        store_smem();
        __syncthreads();
        if (k0 + BK < K) load_regs(k0 + BK);   // overlap LDG with compute below

        #pragma unroll
        for (int kk = 0; kk < BK; kk += 8) {
            uint32_t af[MT][4], bf[NT][2];
            #pragma unroll
            for (int mt = 0; mt < MT; mt++) {
                int r = wm * WM + mt * 16 + group;
                af[mt][0] = __float_as_uint(As[r    ][kk + tg]);
                af[mt][1] = __float_as_uint(As[r + 8][kk + tg]);
                af[mt][2] = __float_as_uint(As[r    ][kk + tg + 4]);
                af[mt][3] = __float_as_uint(As[r + 8][kk + tg + 4]);
            }
            #pragma unroll
            for (int nt = 0; nt < NT; nt++) {
                int c = wn * WN + nt * 8 + group;
                bf[nt][0] = __float_as_uint(Bs[c][kk + tg]);
                bf[nt][1] = __float_as_uint(Bs[c][kk + tg + 4]);
            }
            #pragma unroll
            for (int mt = 0; mt < MT; mt++)
                #pragma unroll
                for (int nt = 0; nt < NT; nt++)
                    mma_tf32(acc[mt][nt], af[mt], bf[nt][0], bf[nt][1]);
        }
        __syncthreads();
    }

    const int bm = blockIdx.y * BM, bn = blockIdx.x * BN;
    #pragma unroll
    for (int mt = 0; mt < MT; mt++)
        #pragma unroll
        for (int nt = 0; nt < NT; nt++) {
            int r0 = bm + wm * WM + mt * 16 + group;
            int c0 = bn + wn * WN + nt * 8 + tg * 2;
            epi(bz, r0,     c0,     acc[mt][nt][0]);
            epi(bz, r0,     c0 + 1, acc[mt][nt][1]);
            epi(bz, r0 + 8, c0,     acc[mt][nt][2]);
            epi(bz, r0 + 8, c0 + 1, acc[mt][nt][3]);
        }
}

// ---------------- LayerNorm over d=64, one warp per row; tf32-round outputs ----------------
__global__ void ln_kernel(float* __restrict__ q, float* __restrict__ k,
                          const float* __restrict__ qg, const float* __restrict__ qb,
                          const float* __restrict__ kg, const float* __restrict__ kb)
{
    int warp = (blockIdx.x * blockDim.x + threadIdx.x) >> 5;
    int lane = threadIdx.x & 31;
    const int total = BHv * Nv;
    float* buf; const float *g, *bt;
    int r = warp;
    if (r < total) { buf = q; g = qg; bt = qb; }
    else           { r -= total; buf = k; g = kg; bt = kb; }
    float* p = buf + (size_t)r * Dv;
    float x0 = p[lane], x1 = p[lane + 32];
    float s = x0 + x1;
    #pragma unroll
    for (int o = 16; o; o >>= 1) s += __shfl_xor_sync(0xFFFFFFFFu, s, o);
    float mu = s * (1.f/64.f);
    float d0 = x0 - mu, d1 = x1 - mu;
    float v2 = d0*d0 + d1*d1;
    #pragma unroll
    for (int o = 16; o; o >>= 1) v2 += __shfl_xor_sync(0xFFFFFFFFu, v2, o);
    float inv = rsqrtf(v2 * (1.f/64.f) + 1e-5f);
    p[lane]      = f2tf32(d0 * inv * g[lane]      + bt[lane]);
    p[lane + 32] = f2tf32(d1 * inv * g[lane + 32] + bt[lane + 32]);
}

// ---------------- mask any-true scan ----------------
__global__ void mask_any_kernel(const uint4* __restrict__ m, int n4, int* flag)
{
    int i = blockIdx.x * blockDim.x + threadIdx.x;
    bool any = false;
    for (; i < n4; i += gridDim.x * blockDim.x) {
        uint4 t = m[i];
        any |= ((t.x | t.y | t.z | t.w) != 0u);
    }
    if (__syncthreads_or(any)) {
        if (threadIdx.x == 0) atomicOr(flag, 1);
    }
}

// ================= fused flash attention (high-occupancy variant) =================
// CTA: 128 threads (4 warps, 16 q-rows each -> 64 q-rows).
// KV tile = 32 rows, 64 tiles, double-buffered cp.async. 3 CTAs/SM.
#define QR 64               // q rows per CTA
#define KT 32               // kv rows per tile
#define PITCH 68            // padded smem row pitch (floats)
#define QTILEF (QR*PITCH)   // 4352 floats
#define KTILEF (KT*PITCH)   // 2176 floats
// smem layout (floats): Q[0..4352) K0 K1 V0 V1 each 2176
#define OFF_K0 QTILEF
#define OFF_K1 (QTILEF + KTILEF)
#define OFF_V0 (QTILEF + 2*KTILEF)
#define OFF_V1 (QTILEF + 3*KTILEF)
#define FLASH_SMEM_F (QTILEF + 4*KTILEF)    // 13056 floats = 52224 B

__global__ void __launch_bounds__(128, 3)
flash_kernel(const float* __restrict__ q, const float* __restrict__ k,
             const float* __restrict__ v, const unsigned char* __restrict__ mask,
             const int* __restrict__ maskflag, float* __restrict__ aout)
{
    extern __shared__ float sm[];
    const int tid  = threadIdx.x;
    const int warp = tid >> 5, lane = tid & 31;
    const int group = lane >> 2, tg = lane & 3;
    const int qtile = blockIdx.x;
    const int bh = blockIdx.y;
    const int bB = bh >> 4, h = bh & 15;
    const int mf = *maskflag;

    const float* qbase = q + (size_t)bh * Nv * Dv + (size_t)qtile * QR * Dv;
    const float* kbase = k + (size_t)bh * Nv * Dv;
    const float* vbase = v + (size_t)bh * Nv * Dv;
    uint32_t sbase = (uint32_t)__cvta_generic_to_shared(sm);

    // ---- stage Q tile (pre-scaled by d^-1/2, exact pow2) ----
    #pragma unroll
    for (int i = 0; i < 8; i++) {
        int idx = tid + i * 128;              // 64 rows x 16 float4
        int row = idx >> 4, c4 = (idx & 15) * 4;
        float4 t = *(const float4*)(qbase + row * Dv + c4);
        t.x *= 0.125f; t.y *= 0.125f; t.z *= 0.125f; t.w *= 0.125f;
        *(float4*)(sm + row * PITCH + c4) = t;
    }
    __syncthreads();

    // Q fragments -> registers (rows warp*16+group, +8)
    uint32_t qf[8][4];
    {
        const float* Qr = sm + (warp * 16 + group) * PITCH;
        #pragma unroll
        for (int kk = 0; kk < 8; kk++) {
            qf[kk][0] = __float_as_uint(Qr[kk*8 + tg]);
            qf[kk][1] = __float_as_uint(Qr[8*PITCH + kk*8 + tg]);
            qf[kk][2] = __float_as_uint(Qr[kk*8 + tg + 4]);
            qf[kk][3] = __float_as_uint(Qr[8*PITCH + kk*8 + tg + 4]);
        }
    }

    auto prefetch = [&](int t, int b) {
        const float* kb = kbase + (size_t)t * KT * Dv;
        const float* vb = vbase + (size_t)t * KT * Dv;
        uint32_t kd = sbase + (uint32_t)((b ? OFF_K1 : OFF_K0)) * 4u;
        uint32_t vd = sbase + (uint32_t)((b ? OFF_V1 : OFF_V0)) * 4u;
        #pragma unroll
        for (int i = 0; i < 4; i++) {
            int idx = tid + i * 128;          // 32 rows x 16 float4
            int row = idx >> 4, c4 = (idx & 15) * 4;
            cp16(kd + (row * PITCH + c4) * 4, kb + row * Dv + c4);
            cp16(vd + (row * PITCH + c4) * 4, vb + row * Dv + c4);
        }
        asm volatile("cp.async.commit_group;\n" ::: "memory");
    };

    prefetch(0, 0);
    prefetch(1, 1);

    // ---- running state ----
    float m0 = -FLT_MAX, m1 = -FLT_MAX, l0 = 0.f, l1 = 0.f;
    float oacc[8][4];
    #pragma unroll
    for (int i = 0; i < 8; i++)
        #pragma unroll
        for (int j = 0; j < 4; j++) oacc[i][j] = 0.f;

    const int qb4 = lane & ~3;
    const int NTILES = Nv / KT;               // 64

    for (int t = 0; t < NTILES; t++) {
        const int buf = t & 1;
        if (t < NTILES - 1) asm volatile("cp.async.wait_group 1;\n" ::: "memory");
        else                asm volatile("cp.async.wait_group 0;\n" ::: "memory");
        __syncthreads();

        const float* Kb = sm + (buf ? OFF_K1 : OFF_K0);
        const float* Vb = sm + (buf ? OFF_V1 : OFF_V0);

        // ---- S = Q K^T (16 x 32 per warp) ----
        float sacc[4][4];
        #pragma unroll
        for (int nt = 0; nt < 4; nt++)
            #pragma unroll
            for (int r = 0; r < 4; r++) sacc[nt][r] = 0.f;

        #pragma unroll
        for (int kk = 0; kk < 8; kk++) {
            #pragma unroll
            for (int nt = 0; nt < 4; nt++) {
                const float* Kr = Kb + (nt * 8 + group) * PITCH + kk * 8;
                uint32_t b0 = __float_as_uint(Kr[tg]);
                uint32_t b1 = __float_as_uint(Kr[tg + 4]);
                mma_tf32(sacc[nt], qf[kk], b0, b1);
            }
        }

        // ---- mask (rare path) ----
        if (mf) {
            const unsigned char* mr0 = mask + ((size_t)(bB * Nv + qtile*QR + warp*16 + group)) * Nv + t * KT;
            const unsigned char* mr1 = mr0 + 8 * Nv;
            #pragma unroll
            for (int nt = 0; nt < 4; nt++) {
                int c = nt * 8 + 2 * tg;
                if (mr0[c])     sacc[nt][0] = -FLT_MAX;
                if (mr0[c + 1]) sacc[nt][1] = -FLT_MAX;
                if (mr1[c])     sacc[nt][2] = -FLT_MAX;
                if (mr1[c + 1]) sacc[nt][3] = -FLT_MAX;
            }
        }

        // ---- online softmax ----
        float mn0 = -FLT_MAX, mn1 = -FLT_MAX;
        #pragma unroll
        for (int nt = 0; nt < 4; nt++) {
            mn0 = fmaxf(mn0, fmaxf(sacc[nt][0], sacc[nt][1]));
            mn1 = fmaxf(mn1, fmaxf(sacc[nt][2], sacc[nt][3]));
        }
        mn0 = fmaxf(mn0, __shfl_xor_sync(0xFFFFFFFFu, mn0, 1));
        mn0 = fmaxf(mn0, __shfl_xor_sync(0xFFFFFFFFu, mn0, 2));
        mn1 = fmaxf(mn1, __shfl_xor_sync(0xFFFFFFFFu, mn1, 1));
        mn1 = fmaxf(mn1, __shfl_xor_sync(0xFFFFFFFFu, mn1, 2));

        float mt0 = fmaxf(m0, mn0), mt1 = fmaxf(m1, mn1);
        float rs0 = 0.f, rs1 = 0.f;
        #pragma unroll
        for (int nt = 0; nt < 4; nt++) {
            float p0 = __expf(sacc[nt][0] - mt0);
            float p1 = __expf(sacc[nt][1] - mt0);
            float p2 = __expf(sacc[nt][2] - mt1);
            float p3 = __expf(sacc[nt][3] - mt1);
            rs0 += p0 + p1; rs1 += p2 + p3;
            sacc[nt][0] = f2tf32(p0); sacc[nt][1] = f2tf32(p1);
            sacc[nt][2] = f2tf32(p2); sacc[nt][3] = f2tf32(p3);
        }
        rs0 += __shfl_xor_sync(0xFFFFFFFFu, rs0, 1);
        rs0 += __shfl_xor_sync(0xFFFFFFFFu, rs0, 2);
        rs1 += __shfl_xor_sync(0xFFFFFFFFu, rs1, 1);
        rs1 += __shfl_xor_sync(0xFFFFFFFFu, rs1, 2);

        // rescale only when some row's max actually moved (skips most tiles)
        if (__any_sync(0xFFFFFFFFu, (mn0 > m0) | (mn1 > m1))) {
            float a0 = __expf(m0 - mt0), a1 = __expf(m1 - mt1);
            l0 = a0 * l0 + rs0;
            l1 = a1 * l1 + rs1;
            #pragma unroll
            for (int i = 0; i < 8; i++) {
                oacc[i][0] *= a0; oacc[i][1] *= a0;
                oacc[i][2] *= a1; oacc[i][3] *= a1;
            }
        } else {
            l0 += rs0; l1 += rs1;
        }
        m0 = mt0; m1 = mt1;

        // ---- O += P V ----
        #pragma unroll
        for (int kc = 0; kc < 4; kc++) {
            int srcA = qb4 + (tg >> 1);
            int srcB = srcA + 2;
            float v0 = __shfl_sync(0xFFFFFFFFu, sacc[kc][0], srcA);
            float v1 = __shfl_sync(0xFFFFFFFFu, sacc[kc][1], srcA);
            float v2 = __shfl_sync(0xFFFFFFFFu, sacc[kc][0], srcB);
            float v3 = __shfl_sync(0xFFFFFFFFu, sacc[kc][1], srcB);
            float w0 = __shfl_sync(0xFFFFFFFFu, sacc[kc][2], srcA);
            float w1 = __shfl_sync(0xFFFFFFFFu, sacc[kc][3], srcA);
            float w2 = __shfl_sync(0xFFFFFFFFu, sacc[kc][2], srcB);
            float w3 = __shfl_sync(0xFFFFFFFFu, sacc[kc][3], srcB);
            uint32_t a[4];
            bool odd = (tg & 1);
            a[0] = __float_as_uint(odd ? v1 : v0);
            a[1] = __float_as_uint(odd ? w1 : w0);
            a[2] = __float_as_uint(odd ? v3 : v2);
            a[3] = __float_as_uint(odd ? w3 : w2);
            #pragma unroll
            for (int nt = 0; nt < 8; nt++) {
                const float* Vr = Vb + (kc * 8 + tg) * PITCH + nt * 8 + group;
                uint32_t b0 = __float_as_uint(Vr[0]);
                uint32_t b1 = __float_as_uint(Vr[4 * PITCH]);
                mma_tf32(oacc[nt], a, b0, b1);
            }
        }

        __syncthreads();
        if (t + 2 < NTILES) prefetch(t + 2, buf);
    }

    // ---- finalize: O /= l, write [b*N+token][h*64+col] ----
    float inv0 = 1.f / l0, inv1 = 1.f / l1;
    int tok0 = qtile * QR + warp * 16 + group;
    float* or0 = aout + ((size_t)(bB * Nv + tok0)) * Cv + h * Dv;
    float* or1 = or0 + 8 * (size_t)Cv;
    #pragma unroll
    for (int nt = 0; nt < 8; nt++) {
        int c = nt * 8 + 2 * tg;
        *(float2*)(or0 + c) = make_float2(oacc[nt][0] * inv0, oacc[nt][1] * inv0);
        *(float2*)(or1 + c) = make_float2(oacc[nt][2] * inv1, oacc[nt][3] * inv1);
    }
}

// ---------------- launch ----------------
extern "C" void kernel_launch(void* const* d_in, const int* in_sizes, int n_in,
                              void* d_out, int out_size)
{
    const float* x            = (const float*)d_in[0];
    const unsigned char* mask = (const unsigned char*)d_in[1];
    const float* w_qkv        = (const float*)d_in[2];
    const float* w_proj       = (const float*)d_in[3];
    const float* b_proj       = (const float*)d_in[4];
    const float* qg           = (const float*)d_in[5];
    const float* qb           = (const float*)d_in[6];
    const float* kg           = (const float*)d_in[7];
    const float* kb           = (const float*)d_in[8];
    float* out                = (float*)d_out;

    void *pq, *pk, *pv, *pa, *pf;
    cudaGetSymbolAddress(&pq, g_q);
    cudaGetSymbolAddress(&pk, g_k);
    cudaGetSymbolAddress(&pv, g_v);
    cudaGetSymbolAddress(&pa, g_attn);
    cudaGetSymbolAddress(&pf, g_maskflag);
    float* q = (float*)pq; float* k = (float*)pk; float* v = (float*)pv;
    float* attn = (float*)pa; int* flag = (int*)pf;

    const int FLASH_SMEM = FLASH_SMEM_F * 4;   // 52224 bytes -> 3 CTAs/SM
    cudaFuncSetAttribute(flash_kernel, cudaFuncAttributeMaxDynamicSharedMemorySize, FLASH_SMEM);

    // 0) mask any-true flag
    cudaMemsetAsync(flag, 0, sizeof(int));
    mask_any_kernel<<<512, 256>>>((const uint4*)mask, (Bv*Nv*Nv)/16, flag);

    // 1) QKV projection: [4096,1024] @ [3072,1024]^T -> q/k/v [b,h,n,d]
    {
        EpiQKV epi{q, k, v};
        dim3 grid(C3/128, MROWS/128, 1);
        gemm_tc_tn<128,128,32,32,64><<<grid, 256>>>(x, w_qkv, Cv, 0, 0, epi);
    }
    // 2) LayerNorm q, k (per-head rows of 64), tf32-rounded outputs
    {
        int warps = 2 * BHv * Nv;
        ln_kernel<<<warps/8, 256>>>(q, k, qg, qb, kg, kb);
    }
    // 3) fused attention: softmax(QK^T * scale + mask) V -> g_attn
    {
        dim3 grid(Nv/QR, BHv);
        flash_kernel<<<grid, 128, FLASH_SMEM>>>(q, k, v, mask, flag, attn);
    }
    // 4) out = attn @ w_proj^T + b_proj
    {
        EpiOut epi{out, b_proj};
        dim3 grid(Cv/128, MROWS/128, 1);
        gemm_tc_tn<128,128,32,32,64><<<grid, 256>>>(attn, w_proj, Cv, 0, 0, epi);
    }
}

// round 6
// speedup vs baseline: 1.1650x; 1.1650x over previous
#include <cuda_runtime.h>
#include <math.h>
#include <float.h>
#include <stdint.h>

// Problem constants
#define Bv 2
#define Nv 2048
#define Cv 1024
#define Hv 16
#define Dv 64
#define BHv (Bv*Hv)        // 32
#define MROWS (Bv*Nv)      // 4096
#define C3 (3*Cv)          // 3072

// Static device scratch (allocation-free rule)
__device__ float g_q[BHv*Nv*Dv];            // 16 MB, [b,h,n,d] (d interleaved)
__device__ float g_k[BHv*Nv*Dv];            // (d interleaved)
__device__ float g_v[BHv*Nv*Dv];            // natural layout
__device__ float g_attn[MROWS*Cv];          // 16 MB, [b*n, h*d]
__device__ int   g_maskflag;

// ---------------- tf32 helpers ----------------
__device__ __forceinline__ float f2tf32(float x) {
    uint32_t u;
    asm("cvt.rna.tf32.f32 %0, %1;" : "=r"(u) : "f"(x));
    return __uint_as_float(u);
}

__device__ __forceinline__ void mma_tf32(float* c, const uint32_t* a, uint32_t b0, uint32_t b1) {
    asm volatile(
        "mma.sync.aligned.m16n8k8.row.col.f32.tf32.tf32.f32 "
        "{%0,%1,%2,%3}, {%4,%5,%6,%7}, {%8,%9}, {%0,%1,%2,%3};\n"
        : "+f"(c[0]), "+f"(c[1]), "+f"(c[2]), "+f"(c[3])
        : "r"(a[0]), "r"(a[1]), "r"(a[2]), "r"(a[3]), "r"(b0), "r"(b1));
}

__device__ __forceinline__ void cp16(uint32_t dst, const void* src) {
    asm volatile("cp.async.cg.shared.global [%0], [%1], 16;\n" :: "r"(dst), "l"(src));
}

// column interleave within 8-blocks: orig j -> pos ((j&3)<<1)|(j>>2)
__device__ __forceinline__ int perm8(int j) { return ((j & 3) << 1) | (j >> 2); }
// inverse: pos p -> orig (p>>1)|((p&1)<<2)
__device__ __forceinline__ int iperm8(int p) { return (p >> 1) | ((p & 1) << 2); }

// ---------------- Epilogue functors ----------------
struct EpiQKV {
    float *q, *k, *v;
    __device__ __forceinline__ void operator()(int bz, int m, int n, float val) const {
        int b   = m >> 11;
        int tok = m & 2047;
        int which = n >> 10;        // 0=q,1=k,2=v
        int h   = (n & 1023) >> 6;
        int dd  = n & 63;
        if (which == 2) {
            val = f2tf32(val);      // V used directly by attention mma
        } else {
            dd = (dd & ~7) | perm8(dd & 7);   // interleave q/k columns
        }
        float* dst = (which == 0) ? q : ((which == 1) ? k : v);
        dst[(((b*Hv + h)*Nv + tok) << 6) + dd] = val;
    }
};

struct EpiOut {
    float* out;
    const float* bias;
    __device__ __forceinline__ void operator()(int bz, int m, int n, float val) const {
        out[(size_t)m*Cv + n] = val + bias[n];
    }
};

// ============ tf32 tensor-core GEMM, TN: C = A(MxK,rm) * B(NxK,rm)^T ============
template<int BM, int BN, int BK, int WM, int WN, class Epi>
__global__ void __launch_bounds__((BM/WM)*(BN/WN)*32)
gemm_tc_tn(const float* __restrict__ A, const float* __restrict__ B,
           int K, long long sA, long long sB, Epi epi)
{
    constexpr int WARPS_M = BM / WM;
    constexpr int WARPS_N = BN / WN;
    constexpr int THREADS = WARPS_M * WARPS_N * 32;
    constexpr int MT = WM / 16;
    constexpr int NT = WN / 8;
    constexpr int PAD = 4;
    constexpr int VPR = BK / 4;

    __shared__ float As[BM][BK + PAD];
    __shared__ float Bs[BN][BK + PAD];

    const int bz = blockIdx.z;
    A += (long long)bz * sA + (long long)blockIdx.y * BM * K;
    B += (long long)bz * sB + (long long)blockIdx.x * BN * K;
    const int tid  = threadIdx.x;
    const int warp = tid >> 5, lane = tid & 31;
    const int wm = warp / WARPS_N, wn = warp % WARPS_N;
    const int group = lane >> 2, tg = lane & 3;

    float acc[MT][NT][4];
    #pragma unroll
    for (int i = 0; i < MT; i++)
        #pragma unroll
        for (int j = 0; j < NT; j++)
            #pragma unroll
            for (int r = 0; r < 4; r++) acc[i][j][r] = 0.f;

    for (int k0 = 0; k0 < K; k0 += BK) {
        #pragma unroll
        for (int i = tid; i < BM * VPR; i += THREADS) {
            int m = i / VPR, kv = i % VPR;
            float4 t = *(const float4*)(A + (long long)m * K + k0 + kv * 4);
            t.x = f2tf32(t.x); t.y = f2tf32(t.y); t.z = f2tf32(t.z); t.w = f2tf32(t.w);
            *(float4*)&As[m][kv * 4] = t;
        }
        #pragma unroll
        for (int i = tid; i < BN * VPR; i += THREADS) {
            int n = i / VPR, kv = i % VPR;
            float4 t = *(const float4*)(B + (long long)n * K + k0 + kv * 4);
            t.x = f2tf32(t.x); t.y = f2tf32(t.y); t.z = f2tf32(t.z); t.w = f2tf32(t.w);
            *(float4*)&Bs[n][kv * 4] = t;
        }
        __syncthreads();

        #pragma unroll
        for (int kk = 0; kk < BK; kk += 8) {
            uint32_t af[MT][4], bf[NT][2];
            #pragma unroll
            for (int mt = 0; mt < MT; mt++) {
                int r = wm * WM + mt * 16 + group;
                af[mt][0] = __float_as_uint(As[r    ][kk + tg]);
                af[mt][1] = __float_as_uint(As[r + 8][kk + tg]);
                af[mt][2] = __float_as_uint(As[r    ][kk + tg + 4]);
                af[mt][3] = __float_as_uint(As[r + 8][kk + tg + 4]);
            }
            #pragma unroll
            for (int nt = 0; nt < NT; nt++) {
                int c = wn * WN + nt * 8 + group;
                bf[nt][0] = __float_as_uint(Bs[c][kk + tg]);
                bf[nt][1] = __float_as_uint(Bs[c][kk + tg + 4]);
            }
            #pragma unroll
            for (int mt = 0; mt < MT; mt++)
                #pragma unroll
                for (int nt = 0; nt < NT; nt++)
                    mma_tf32(acc[mt][nt], af[mt], bf[nt][0], bf[nt][1]);
        }
        __syncthreads();
    }

    const int bm = blockIdx.y * BM, bn = blockIdx.x * BN;
    #pragma unroll
    for (int mt = 0; mt < MT; mt++)
        #pragma unroll
        for (int nt = 0; nt < NT; nt++) {
            int r0 = bm + wm * WM + mt * 16 + group;
            int c0 = bn + wn * WN + nt * 8 + tg * 2;
            epi(bz, r0,     c0,     acc[mt][nt][0]);
            epi(bz, r0,     c0 + 1, acc[mt][nt][1]);
            epi(bz, r0 + 8, c0,     acc[mt][nt][2]);
            epi(bz, r0 + 8, c0 + 1, acc[mt][nt][3]);
        }
}

// ---------------- LayerNorm over d=64 (interleaved layout), one warp per row ----------------
__global__ void ln_kernel(float* __restrict__ q, float* __restrict__ k,
                          const float* __restrict__ qg, const float* __restrict__ qb,
                          const float* __restrict__ kg, const float* __restrict__ kb)
{
    int warp = (blockIdx.x * blockDim.x + threadIdx.x) >> 5;
    int lane = threadIdx.x & 31;
    const int total = BHv * Nv;
    float* buf; const float *g, *bt;
    int r = warp;
    if (r < total) { buf = q; g = qg; bt = qb; }
    else           { r -= total; buf = k; g = kg; bt = kb; }
    float* p = buf + (size_t)r * Dv;
    // positions lane, lane+32 hold original columns o0, o1
    int p0 = lane, p1 = lane + 32;
    int o0 = (p0 & ~7) | iperm8(p0 & 7);
    int o1 = (p1 & ~7) | iperm8(p1 & 7);
    float x0 = p[p0], x1 = p[p1];
    float s = x0 + x1;
    #pragma unroll
    for (int o = 16; o; o >>= 1) s += __shfl_xor_sync(0xFFFFFFFFu, s, o);
    float mu = s * (1.f/64.f);
    float d0 = x0 - mu, d1 = x1 - mu;
    float v2 = d0*d0 + d1*d1;
    #pragma unroll
    for (int o = 16; o; o >>= 1) v2 += __shfl_xor_sync(0xFFFFFFFFu, v2, o);
    float inv = rsqrtf(v2 * (1.f/64.f) + 1e-5f);
    p[p0] = f2tf32(d0 * inv * g[o0] + bt[o0]);
    p[p1] = f2tf32(d1 * inv * g[o1] + bt[o1]);
}

// ---------------- mask any-true scan ----------------
__global__ void mask_any_kernel(const uint4* __restrict__ m, int n4, int* flag)
{
    int i = blockIdx.x * blockDim.x + threadIdx.x;
    bool any = false;
    for (; i < n4; i += gridDim.x * blockDim.x) {
        uint4 t = m[i];
        any |= ((t.x | t.y | t.z | t.w) != 0u);
    }
    if (__syncthreads_or(any)) {
        if (threadIdx.x == 0) atomicOr(flag, 1);
    }
}

// ================= fused flash attention =================
// CTA: 128 threads (4 warps, 64 q-rows). KV tile 32, double-buffered. 4 CTAs/SM.
#define QR 64
#define KT 32
#define PITCH 72            // 8g-mod-32 stride: conflict-free LDS.64
#define QTILEF (QR*PITCH)   // 4608 floats
#define KTILEF (KT*PITCH)   // 2304 floats
#define OFF_K0 QTILEF
#define OFF_K1 (QTILEF + KTILEF)
#define OFF_V0 (QTILEF + 2*KTILEF)
#define OFF_V1 (QTILEF + 3*KTILEF)
#define FLASH_SMEM_F (QTILEF + 4*KTILEF)    // 13824 floats = 55296 B

__global__ void __launch_bounds__(128, 4)
flash_kernel(const float* __restrict__ q, const float* __restrict__ k,
             const float* __restrict__ v, const unsigned char* __restrict__ mask,
             const int* __restrict__ maskflag, float* __restrict__ aout)
{
    extern __shared__ float sm[];
    const int tid  = threadIdx.x;
    const int warp = tid >> 5, lane = tid & 31;
    const int group = lane >> 2, tg = lane & 3;
    const int qtile = blockIdx.x;
    const int bh = blockIdx.y;
    const int bB = bh >> 4, h = bh & 15;
    const int mf = *maskflag;

    const float* qbase = q + (size_t)bh * Nv * Dv + (size_t)qtile * QR * Dv;
    const float* kbase = k + (size_t)bh * Nv * Dv;
    const float* vbase = v + (size_t)bh * Nv * Dv;
    uint32_t sbase = (uint32_t)__cvta_generic_to_shared(sm);

    // ---- stage Q tile (pre-scaled by d^-1/2) ----
    #pragma unroll
    for (int i = 0; i < 8; i++) {
        int idx = tid + i * 128;              // 64 rows x 16 float4
        int row = idx >> 4, c4 = (idx & 15) * 4;
        float4 t = *(const float4*)(qbase + row * Dv + c4);
        t.x *= 0.125f; t.y *= 0.125f; t.z *= 0.125f; t.w *= 0.125f;
        *(float4*)(sm + row * PITCH + c4) = t;
    }
    __syncthreads();

    auto prefetch = [&](int t, int b) {
        const float* kb = kbase + (size_t)t * KT * Dv;
        const float* vb = vbase + (size_t)t * KT * Dv;
        uint32_t kd = sbase + (uint32_t)((b ? OFF_K1 : OFF_K0)) * 4u;
        uint32_t vd = sbase + (uint32_t)((b ? OFF_V1 : OFF_V0)) * 4u;
        #pragma unroll
        for (int i = 0; i < 4; i++) {
            int idx = tid + i * 128;          // 32 rows x 16 float4
            int row = idx >> 4, c4 = (idx & 15) * 4;
            cp16(kd + (row * PITCH + c4) * 4, kb + row * Dv + c4);
            cp16(vd + (row * PITCH + c4) * 4, vb + row * Dv + c4);
        }
        asm volatile("cp.async.commit_group;\n" ::: "memory");
    };

    prefetch(0, 0);
    prefetch(1, 1);

    // ---- running state ----
    float m0 = -FLT_MAX, m1 = -FLT_MAX, l0 = 0.f, l1 = 0.f;
    float oacc[8][4];
    #pragma unroll
    for (int i = 0; i < 8; i++)
        #pragma unroll
        for (int j = 0; j < 4; j++) oacc[i][j] = 0.f;

    const int qb4 = lane & ~3;
    const int NTILES = Nv / KT;               // 64
    const float* Qr0 = sm + (warp * 16 + group) * PITCH + tg * 2;
    const float* Qr1 = Qr0 + 8 * PITCH;

    for (int t = 0; t < NTILES; t++) {
        const int buf = t & 1;
        if (t < NTILES - 1) asm volatile("cp.async.wait_group 1;\n" ::: "memory");
        else                asm volatile("cp.async.wait_group 0;\n" ::: "memory");
        __syncthreads();

        const float* Kb = sm + (buf ? OFF_K1 : OFF_K0);
        const float* Vb = sm + (buf ? OFF_V1 : OFF_V0);

        // ---- S = Q K^T (16 x 32 per warp); interleaved layout -> LDS.64 frags ----
        float sacc[4][4];
        #pragma unroll
        for (int nt = 0; nt < 4; nt++)
            #pragma unroll
            for (int r = 0; r < 4; r++) sacc[nt][r] = 0.f;

        #pragma unroll
        for (int kk = 0; kk < 8; kk++) {
            float2 qa = *(const float2*)(Qr0 + kk * 8);
            float2 qb = *(const float2*)(Qr1 + kk * 8);
            uint32_t a[4] = { __float_as_uint(qa.x), __float_as_uint(qb.x),
                              __float_as_uint(qa.y), __float_as_uint(qb.y) };
            #pragma unroll
            for (int nt = 0; nt < 4; nt++) {
                float2 kf = *(const float2*)(Kb + (nt * 8 + group) * PITCH + kk * 8 + tg * 2);
                mma_tf32(sacc[nt], a, __float_as_uint(kf.x), __float_as_uint(kf.y));
            }
        }

        // ---- mask (rare path) ----
        if (mf) {
            const unsigned char* mr0 = mask + ((size_t)(bB * Nv + qtile*QR + warp*16 + group)) * Nv + t * KT;
            const unsigned char* mr1 = mr0 + 8 * Nv;
            #pragma unroll
            for (int nt = 0; nt < 4; nt++) {
                int c = nt * 8 + 2 * tg;
                if (mr0[c])     sacc[nt][0] = -FLT_MAX;
                if (mr0[c + 1]) sacc[nt][1] = -FLT_MAX;
                if (mr1[c])     sacc[nt][2] = -FLT_MAX;
                if (mr1[c + 1]) sacc[nt][3] = -FLT_MAX;
            }
        }

        // ---- online softmax ----
        float mn0 = -FLT_MAX, mn1 = -FLT_MAX;
        #pragma unroll
        for (int nt = 0; nt < 4; nt++) {
            mn0 = fmaxf(mn0, fmaxf(sacc[nt][0], sacc[nt][1]));
            mn1 = fmaxf(mn1, fmaxf(sacc[nt][2], sacc[nt][3]));
        }
        mn0 = fmaxf(mn0, __shfl_xor_sync(0xFFFFFFFFu, mn0, 1));
        mn0 = fmaxf(mn0, __shfl_xor_sync(0xFFFFFFFFu, mn0, 2));
        mn1 = fmaxf(mn1, __shfl_xor_sync(0xFFFFFFFFu, mn1, 1));
        mn1 = fmaxf(mn1, __shfl_xor_sync(0xFFFFFFFFu, mn1, 2));

        float mt0 = fmaxf(m0, mn0), mt1 = fmaxf(m1, mn1);
        float rs0 = 0.f, rs1 = 0.f;
        #pragma unroll
        for (int nt = 0; nt < 4; nt++) {
            float p0 = __expf(sacc[nt][0] - mt0);
            float p1 = __expf(sacc[nt][1] - mt0);
            float p2 = __expf(sacc[nt][2] - mt1);
            float p3 = __expf(sacc[nt][3] - mt1);
            rs0 += p0 + p1; rs1 += p2 + p3;
            sacc[nt][0] = f2tf32(p0); sacc[nt][1] = f2tf32(p1);
            sacc[nt][2] = f2tf32(p2); sacc[nt][3] = f2tf32(p3);
        }
        rs0 += __shfl_xor_sync(0xFFFFFFFFu, rs0, 1);
        rs0 += __shfl_xor_sync(0xFFFFFFFFu, rs0, 2);
        rs1 += __shfl_xor_sync(0xFFFFFFFFu, rs1, 1);
        rs1 += __shfl_xor_sync(0xFFFFFFFFu, rs1, 2);

        if (__any_sync(0xFFFFFFFFu, (mn0 > m0) | (mn1 > m1))) {
            float a0 = __expf(m0 - mt0), a1 = __expf(m1 - mt1);
            l0 = a0 * l0 + rs0;
            l1 = a1 * l1 + rs1;
            #pragma unroll
            for (int i = 0; i < 8; i++) {
                oacc[i][0] *= a0; oacc[i][1] *= a0;
                oacc[i][2] *= a1; oacc[i][3] *= a1;
            }
        } else {
            l0 += rs0; l1 += rs1;
        }
        m0 = mt0; m1 = mt1;

        // ---- O += P V ----
        #pragma unroll
        for (int kc = 0; kc < 4; kc++) {
            int srcA = qb4 + (tg >> 1);
            int srcB = srcA + 2;
            float v0 = __shfl_sync(0xFFFFFFFFu, sacc[kc][0], srcA);
            float v1 = __shfl_sync(0xFFFFFFFFu, sacc[kc][1], srcA);
            float v2 = __shfl_sync(0xFFFFFFFFu, sacc[kc][0], srcB);
            float v3 = __shfl_sync(0xFFFFFFFFu, sacc[kc][1], srcB);
            float w0 = __shfl_sync(0xFFFFFFFFu, sacc[kc][2], srcA);
            float w1 = __shfl_sync(0xFFFFFFFFu, sacc[kc][3], srcA);
            float w2 = __shfl_sync(0xFFFFFFFFu, sacc[kc][2], srcB);
            float w3 = __shfl_sync(0xFFFFFFFFu, sacc[kc][3], srcB);
            uint32_t a[4];
            bool odd = (tg & 1);
            a[0] = __float_as_uint(odd ? v1 : v0);
            a[1] = __float_as_uint(odd ? w1 : w0);
            a[2] = __float_as_uint(odd ? v3 : v2);
            a[3] = __float_as_uint(odd ? w3 : w2);
            #pragma unroll
            for (int nt = 0; nt < 8; nt++) {
                const float* Vr = Vb + (kc * 8 + tg) * PITCH + nt * 8 + group;
                uint32_t b0 = __float_as_uint(Vr[0]);
                uint32_t b1 = __float_as_uint(Vr[4 * PITCH]);
                mma_tf32(oacc[nt], a, b0, b1);
            }
        }

        __syncthreads();
        if (t + 2 < NTILES) prefetch(t + 2, buf);
    }

    // ---- finalize ----
    float inv0 = 1.f / l0, inv1 = 1.f / l1;
    int tok0 = qtile * QR + warp * 16 + group;
    float* or0 = aout + ((size_t)(bB * Nv + tok0)) * Cv + h * Dv;
    float* or1 = or0 + 8 * (size_t)Cv;
    #pragma unroll
    for (int nt = 0; nt < 8; nt++) {
        int c = nt * 8 + 2 * tg;
        *(float2*)(or0 + c) = make_float2(oacc[nt][0] * inv0, oacc[nt][1] * inv0);
        *(float2*)(or1 + c) = make_float2(oacc[nt][2] * inv1, oacc[nt][3] * inv1);
    }
}

// ---------------- launch ----------------
extern "C" void kernel_launch(void* const* d_in, const int* in_sizes, int n_in,
                              void* d_out, int out_size)
{
    const float* x            = (const float*)d_in[0];
    const unsigned char* mask = (const unsigned char*)d_in[1];
    const float* w_qkv        = (const float*)d_in[2];
    const float* w_proj       = (const float*)d_in[3];
    const float* b_proj       = (const float*)d_in[4];
    const float* qg           = (const float*)d_in[5];
    const float* qb           = (const float*)d_in[6];
    const float* kg           = (const float*)d_in[7];
    const float* kb           = (const float*)d_in[8];
    float* out                = (float*)d_out;

    void *pq, *pk, *pv, *pa, *pf;
    cudaGetSymbolAddress(&pq, g_q);
    cudaGetSymbolAddress(&pk, g_k);
    cudaGetSymbolAddress(&pv, g_v);
    cudaGetSymbolAddress(&pa, g_attn);
    cudaGetSymbolAddress(&pf, g_maskflag);
    float* q = (float*)pq; float* k = (float*)pk; float* v = (float*)pv;
    float* attn = (float*)pa; int* flag = (int*)pf;

    const int FLASH_SMEM = FLASH_SMEM_F * 4;   // 55296 bytes -> 4 CTAs/SM
    cudaFuncSetAttribute(flash_kernel, cudaFuncAttributeMaxDynamicSharedMemorySize, FLASH_SMEM);

    // 0) mask any-true flag
    cudaMemsetAsync(flag, 0, sizeof(int));
    mask_any_kernel<<<512, 256>>>((const uint4*)mask, (Bv*Nv*Nv)/16, flag);

    // 1) QKV projection
    {
        EpiQKV epi{q, k, v};
        dim3 grid(C3/128, MROWS/128, 1);
        gemm_tc_tn<128,128,32,32,64><<<grid, 256>>>(x, w_qkv, Cv, 0, 0, epi);
    }
    // 2) LayerNorm q, k
    {
        int warps = 2 * BHv * Nv;
        ln_kernel<<<warps/8, 256>>>(q, k, qg, qb, kg, kb);
    }
    // 3) fused attention
    {
        dim3 grid(Nv/QR, BHv);
        flash_kernel<<<grid, 128, FLASH_SMEM>>>(q, k, v, mask, flag, attn);
    }
    // 4) out = attn @ w_proj^T + b_proj
    {
        EpiOut epi{out, b_proj};
        dim3 grid(Cv/128, MROWS/128, 1);
        gemm_tc_tn<128,128,32,32,64><<<grid, 256>>>(attn, w_proj, Cv, 0, 0, epi);
    }
}

// round 7
// speedup vs baseline: 1.1982x; 1.0285x over previous
#include <cuda_runtime.h>
#include <math.h>
#include <float.h>
#include <stdint.h>

// Problem constants
#define Bv 2
#define Nv 2048
#define Cv 1024
#define Hv 16
#define Dv 64
#define BHv (Bv*Hv)        // 32
#define MROWS (Bv*Nv)      // 4096
#define C3 (3*Cv)          // 3072

// Static device scratch (allocation-free rule)
__device__ float g_q[BHv*Nv*Dv];            // [b,h,n,d] (d interleaved in 8-blocks)
__device__ float g_k[BHv*Nv*Dv];            // [b,h,n,d] (d interleaved)
__device__ float g_v[BHv*Nv*Dv];            // [b,h,d,n] TRANSPOSED (n interleaved)
__device__ float g_attn[MROWS*Cv];          // [b*n, h*d]
__device__ int   g_maskflag;

// ---------------- tf32 helpers ----------------
__device__ __forceinline__ float f2tf32(float x) {
    uint32_t u;
    asm("cvt.rna.tf32.f32 %0, %1;" : "=r"(u) : "f"(x));
    return __uint_as_float(u);
}

__device__ __forceinline__ void mma_tf32(float* c, const uint32_t* a, uint32_t b0, uint32_t b1) {
    asm volatile(
        "mma.sync.aligned.m16n8k8.row.col.f32.tf32.tf32.f32 "
        "{%0,%1,%2,%3}, {%4,%5,%6,%7}, {%8,%9}, {%0,%1,%2,%3};\n"
        : "+f"(c[0]), "+f"(c[1]), "+f"(c[2]), "+f"(c[3])
        : "r"(a[0]), "r"(a[1]), "r"(a[2]), "r"(a[3]), "r"(b0), "r"(b1));
}

__device__ __forceinline__ void cp16(uint32_t dst, const void* src) {
    asm volatile("cp.async.cg.shared.global [%0], [%1], 16;\n" :: "r"(dst), "l"(src));
}

// interleave within 8-blocks: orig j -> pos ((j&3)<<1)|(j>>2)
__device__ __forceinline__ int perm8(int j) { return ((j & 3) << 1) | (j >> 2); }
__device__ __forceinline__ int iperm8(int p) { return (p >> 1) | ((p & 1) << 2); }

// ---------------- Epilogue functors ----------------
struct EpiQKV {
    float *q, *k, *v;
    __device__ __forceinline__ void operator()(int bz, int m, int n, float val) const {
        int b   = m >> 11;
        int tok = m & 2047;
        int which = n >> 10;        // 0=q,1=k,2=v
        int h   = (n & 1023) >> 6;
        int dd  = n & 63;
        if (which == 2) {
            // V: transposed [b,h][d][n], token interleaved, tf32-rounded
            int tokp = (tok & ~7) | perm8(tok & 7);
            v[(((b*Hv + h)*Dv + dd) << 11) + tokp] = f2tf32(val);
        } else {
            int dp = (dd & ~7) | perm8(dd & 7);   // interleave q/k d-columns
            float* dst = (which == 0) ? q : k;
            dst[(((b*Hv + h)*Nv + tok) << 6) + dp] = val;
        }
    }
};

struct EpiOut {
    float* out;
    const float* bias;
    __device__ __forceinline__ void operator()(int bz, int m, int n, float val) const {
        out[(size_t)m*Cv + n] = val + bias[n];
    }
};

// ============ tf32 tensor-core GEMM, TN: C = A(MxK,rm) * B(NxK,rm)^T ============
template<int BM, int BN, int BK, int WM, int WN, class Epi>
__global__ void __launch_bounds__((BM/WM)*(BN/WN)*32)
gemm_tc_tn(const float* __restrict__ A, const float* __restrict__ B,
           int K, long long sA, long long sB, Epi epi)
{
    constexpr int WARPS_M = BM / WM;
    constexpr int WARPS_N = BN / WN;
    constexpr int THREADS = WARPS_M * WARPS_N * 32;
    constexpr int MT = WM / 16;
    constexpr int NT = WN / 8;
    constexpr int PAD = 4;
    constexpr int VPR = BK / 4;

    __shared__ float As[BM][BK + PAD];
    __shared__ float Bs[BN][BK + PAD];

    const int bz = blockIdx.z;
    A += (long long)bz * sA + (long long)blockIdx.y * BM * K;
    B += (long long)bz * sB + (long long)blockIdx.x * BN * K;
    const int tid  = threadIdx.x;
    const int warp = tid >> 5, lane = tid & 31;
    const int wm = warp / WARPS_N, wn = warp % WARPS_N;
    const int group = lane >> 2, tg = lane & 3;

    float acc[MT][NT][4];
    #pragma unroll
    for (int i = 0; i < MT; i++)
        #pragma unroll
        for (int j = 0; j < NT; j++)
            #pragma unroll
            for (int r = 0; r < 4; r++) acc[i][j][r] = 0.f;

    for (int k0 = 0; k0 < K; k0 += BK) {
        #pragma unroll
        for (int i = tid; i < BM * VPR; i += THREADS) {
            int m = i / VPR, kv = i % VPR;
            float4 t = *(const float4*)(A + (long long)m * K + k0 + kv * 4);
            t.x = f2tf32(t.x); t.y = f2tf32(t.y); t.z = f2tf32(t.z); t.w = f2tf32(t.w);
            *(float4*)&As[m][kv * 4] = t;
        }
        #pragma unroll
        for (int i = tid; i < BN * VPR; i += THREADS) {
            int n = i / VPR, kv = i % VPR;
            float4 t = *(const float4*)(B + (long long)n * K + k0 + kv * 4);
            t.x = f2tf32(t.x); t.y = f2tf32(t.y); t.z = f2tf32(t.z); t.w = f2tf32(t.w);
            *(float4*)&Bs[n][kv * 4] = t;
        }
        __syncthreads();

        #pragma unroll
        for (int kk = 0; kk < BK; kk += 8) {
            uint32_t af[MT][4], bf[NT][2];
            #pragma unroll
            for (int mt = 0; mt < MT; mt++) {
                int r = wm * WM + mt * 16 + group;
                af[mt][0] = __float_as_uint(As[r    ][kk + tg]);
                af[mt][1] = __float_as_uint(As[r + 8][kk + tg]);
                af[mt][2] = __float_as_uint(As[r    ][kk + tg + 4]);
                af[mt][3] = __float_as_uint(As[r + 8][kk + tg + 4]);
            }
            #pragma unroll
            for (int nt = 0; nt < NT; nt++) {
                int c = wn * WN + nt * 8 + group;
                bf[nt][0] = __float_as_uint(Bs[c][kk + tg]);
                bf[nt][1] = __float_as_uint(Bs[c][kk + tg + 4]);
            }
            #pragma unroll
            for (int mt = 0; mt < MT; mt++)
                #pragma unroll
                for (int nt = 0; nt < NT; nt++)
                    mma_tf32(acc[mt][nt], af[mt], bf[nt][0], bf[nt][1]);
        }
        __syncthreads();
    }

    const int bm = blockIdx.y * BM, bn = blockIdx.x * BN;
    #pragma unroll
    for (int mt = 0; mt < MT; mt++)
        #pragma unroll
        for (int nt = 0; nt < NT; nt++) {
            int r0 = bm + wm * WM + mt * 16 + group;
            int c0 = bn + wn * WN + nt * 8 + tg * 2;
            epi(bz, r0,     c0,     acc[mt][nt][0]);
            epi(bz, r0,     c0 + 1, acc[mt][nt][1]);
            epi(bz, r0 + 8, c0,     acc[mt][nt][2]);
            epi(bz, r0 + 8, c0 + 1, acc[mt][nt][3]);
        }
}

// ---------------- LayerNorm over d=64 (interleaved layout), one warp per row ----------------
__global__ void ln_kernel(float* __restrict__ q, float* __restrict__ k,
                          const float* __restrict__ qg, const float* __restrict__ qb,
                          const float* __restrict__ kg, const float* __restrict__ kb)
{
    int warp = (blockIdx.x * blockDim.x + threadIdx.x) >> 5;
    int lane = threadIdx.x & 31;
    const int total = BHv * Nv;
    float* buf; const float *g, *bt;
    int r = warp;
    if (r < total) { buf = q; g = qg; bt = qb; }
    else           { r -= total; buf = k; g = kg; bt = kb; }
    float* p = buf + (size_t)r * Dv;
    int p0 = lane, p1 = lane + 32;
    int o0 = (p0 & ~7) | iperm8(p0 & 7);
    int o1 = (p1 & ~7) | iperm8(p1 & 7);
    float x0 = p[p0], x1 = p[p1];
    float s = x0 + x1;
    #pragma unroll
    for (int o = 16; o; o >>= 1) s += __shfl_xor_sync(0xFFFFFFFFu, s, o);
    float mu = s * (1.f/64.f);
    float d0 = x0 - mu, d1 = x1 - mu;
    float v2 = d0*d0 + d1*d1;
    #pragma unroll
    for (int o = 16; o; o >>= 1) v2 += __shfl_xor_sync(0xFFFFFFFFu, v2, o);
    float inv = rsqrtf(v2 * (1.f/64.f) + 1e-5f);
    p[p0] = f2tf32(d0 * inv * g[o0] + bt[o0]);
    p[p1] = f2tf32(d1 * inv * g[o1] + bt[o1]);
}

// ---------------- mask any-true scan ----------------
__global__ void mask_any_kernel(const uint4* __restrict__ m, int n4, int* flag)
{
    int i = blockIdx.x * blockDim.x + threadIdx.x;
    bool any = false;
    for (; i < n4; i += gridDim.x * blockDim.x) {
        uint4 t = m[i];
        any |= ((t.x | t.y | t.z | t.w) != 0u);
    }
    if (__syncthreads_or(any)) {
        if (threadIdx.x == 0) atomicOr(flag, 1);
    }
}

// ================= fused flash attention =================
// CTA: 128 threads (4 warps, 64 q-rows). KV tile 32 tokens, double-buffered.
#define QR 64
#define KT 32
#define PITCH 72            // Q/K row pitch (floats): conflict-free LDS.64
#define VPITCH 40           // V^T row pitch (floats): conflict-free LDS.64
#define QTILEF (QR*PITCH)   // 4608
#define KTILEF (KT*PITCH)   // 2304
#define VTILEF (Dv*VPITCH)  // 2560
#define OFF_K0 QTILEF
#define OFF_K1 (QTILEF + KTILEF)
#define OFF_V0 (QTILEF + 2*KTILEF)
#define OFF_V1 (QTILEF + 2*KTILEF + VTILEF)
#define FLASH_SMEM_F (QTILEF + 2*KTILEF + 2*VTILEF)   // 14336 floats = 57344 B

template<bool MASKED>
__global__ void __launch_bounds__(128, 4)
flash_kernel(const float* __restrict__ q, const float* __restrict__ k,
             const float* __restrict__ v, const unsigned char* __restrict__ mask,
             const int* __restrict__ maskflag, float* __restrict__ aout)
{
    const int mf = *maskflag;
    if (MASKED ? (mf == 0) : (mf != 0)) return;   // exactly one instance runs

    extern __shared__ float sm[];
    const int tid  = threadIdx.x;
    const int warp = tid >> 5, lane = tid & 31;
    const int group = lane >> 2, tg = lane & 3;
    const int qtile = blockIdx.x;
    const int bh = blockIdx.y;
    const int bB = bh >> 4, h = bh & 15;

    const float* qbase = q + (size_t)bh * Nv * Dv + (size_t)qtile * QR * Dv;
    const float* kbase = k + (size_t)bh * Nv * Dv;
    const float* vbase = v + (size_t)bh * Nv * Dv;      // [d][n] layout
    uint32_t sbase = (uint32_t)__cvta_generic_to_shared(sm);

    // ---- stage Q tile (pre-scaled by d^-1/2) ----
    #pragma unroll
    for (int i = 0; i < 8; i++) {
        int idx = tid + i * 128;              // 64 rows x 16 float4
        int row = idx >> 4, c4 = (idx & 15) * 4;
        float4 t = *(const float4*)(qbase + row * Dv + c4);
        t.x *= 0.125f; t.y *= 0.125f; t.z *= 0.125f; t.w *= 0.125f;
        *(float4*)(sm + row * PITCH + c4) = t;
    }
    __syncthreads();

    auto prefetch = [&](int t, int b) {
        const float* kb = kbase + (size_t)t * KT * Dv;
        const float* vb = vbase + (size_t)t * KT;       // column block of V^T
        uint32_t kd = sbase + (uint32_t)((b ? OFF_K1 : OFF_K0)) * 4u;
        uint32_t vd = sbase + (uint32_t)((b ? OFF_V1 : OFF_V0)) * 4u;
        #pragma unroll
        for (int i = 0; i < 4; i++) {
            int idx = tid + i * 128;
            {   // K: 32 rows x 16 float4
                int row = idx >> 4, c4 = (idx & 15) * 4;
                cp16(kd + (row * PITCH + c4) * 4, kb + row * Dv + c4);
            }
            {   // V^T: 64 rows x 8 float4
                int row = idx >> 3, c4 = (idx & 7) * 4;
                cp16(vd + (row * VPITCH + c4) * 4, vb + (size_t)row * Nv + c4);
            }
        }
        asm volatile("cp.async.commit_group;\n" ::: "memory");
    };

    prefetch(0, 0);
    prefetch(1, 1);

    // ---- running state ----
    float m0 = -FLT_MAX, m1 = -FLT_MAX, l0 = 0.f, l1 = 0.f;
    float oacc[8][4];
    #pragma unroll
    for (int i = 0; i < 8; i++)
        #pragma unroll
        for (int j = 0; j < 4; j++) oacc[i][j] = 0.f;

    const int qb4 = lane & ~3;
    const int NTILES = Nv / KT;               // 64
    const float* Qr0 = sm + (warp * 16 + group) * PITCH + tg * 2;
    const float* Qr1 = Qr0 + 8 * PITCH;

    for (int t = 0; t < NTILES; t++) {
        const int buf = t & 1;
        if (t < NTILES - 1) asm volatile("cp.async.wait_group 1;\n" ::: "memory");
        else                asm volatile("cp.async.wait_group 0;\n" ::: "memory");
        __syncthreads();

        const float* Kb = sm + (buf ? OFF_K1 : OFF_K0);
        const float* Vb = sm + (buf ? OFF_V1 : OFF_V0);

        // ---- S = Q K^T (16 x 32 per warp), LDS.64 fragments ----
        float sacc[4][4];
        #pragma unroll
        for (int nt = 0; nt < 4; nt++)
            #pragma unroll
            for (int r = 0; r < 4; r++) sacc[nt][r] = 0.f;

        #pragma unroll
        for (int kk = 0; kk < 8; kk++) {
            float2 qa = *(const float2*)(Qr0 + kk * 8);
            float2 qb = *(const float2*)(Qr1 + kk * 8);
            uint32_t a[4] = { __float_as_uint(qa.x), __float_as_uint(qb.x),
                              __float_as_uint(qa.y), __float_as_uint(qb.y) };
            #pragma unroll
            for (int nt = 0; nt < 4; nt++) {
                float2 kf = *(const float2*)(Kb + (nt * 8 + group) * PITCH + kk * 8 + tg * 2);
                mma_tf32(sacc[nt], a, __float_as_uint(kf.x), __float_as_uint(kf.y));
            }
        }

        float rs0 = 0.f, rs1 = 0.f;
        if (MASKED) {
            // ---- mask + full online softmax (general path) ----
            const unsigned char* mr0 = mask + ((size_t)(bB * Nv + qtile*QR + warp*16 + group)) * Nv + t * KT;
            const unsigned char* mr1 = mr0 + 8 * Nv;
            #pragma unroll
            for (int nt = 0; nt < 4; nt++) {
                int c = nt * 8 + 2 * tg;
                if (mr0[c])     sacc[nt][0] = -FLT_MAX;
                if (mr0[c + 1]) sacc[nt][1] = -FLT_MAX;
                if (mr1[c])     sacc[nt][2] = -FLT_MAX;
                if (mr1[c + 1]) sacc[nt][3] = -FLT_MAX;
            }
            float mn0 = -FLT_MAX, mn1 = -FLT_MAX;
            #pragma unroll
            for (int nt = 0; nt < 4; nt++) {
                mn0 = fmaxf(mn0, fmaxf(sacc[nt][0], sacc[nt][1]));
                mn1 = fmaxf(mn1, fmaxf(sacc[nt][2], sacc[nt][3]));
            }
            mn0 = fmaxf(mn0, __shfl_xor_sync(0xFFFFFFFFu, mn0, 1));
            mn0 = fmaxf(mn0, __shfl_xor_sync(0xFFFFFFFFu, mn0, 2));
            mn1 = fmaxf(mn1, __shfl_xor_sync(0xFFFFFFFFu, mn1, 1));
            mn1 = fmaxf(mn1, __shfl_xor_sync(0xFFFFFFFFu, mn1, 2));
            float mt0 = fmaxf(m0, mn0), mt1 = fmaxf(m1, mn1);
            #pragma unroll
            for (int nt = 0; nt < 4; nt++) {
                float p0 = __expf(sacc[nt][0] - mt0);
                float p1 = __expf(sacc[nt][1] - mt0);
                float p2 = __expf(sacc[nt][2] - mt1);
                float p3 = __expf(sacc[nt][3] - mt1);
                rs0 += p0 + p1; rs1 += p2 + p3;
                sacc[nt][0] = f2tf32(p0); sacc[nt][1] = f2tf32(p1);
                sacc[nt][2] = f2tf32(p2); sacc[nt][3] = f2tf32(p3);
            }
            rs0 += __shfl_xor_sync(0xFFFFFFFFu, rs0, 1);
            rs0 += __shfl_xor_sync(0xFFFFFFFFu, rs0, 2);
            rs1 += __shfl_xor_sync(0xFFFFFFFFu, rs1, 1);
            rs1 += __shfl_xor_sync(0xFFFFFFFFu, rs1, 2);
            if (__any_sync(0xFFFFFFFFu, (mn0 > m0) | (mn1 > m1))) {
                float a0 = __expf(m0 - mt0), a1 = __expf(m1 - mt1);
                l0 = a0 * l0 + rs0;
                l1 = a1 * l1 + rs1;
                #pragma unroll
                for (int i = 0; i < 8; i++) {
                    oacc[i][0] *= a0; oacc[i][1] *= a0;
                    oacc[i][2] *= a1; oacc[i][3] *= a1;
                }
            } else {
                l0 += rs0; l1 += rs1;
            }
            m0 = mt0; m1 = mt1;
        } else {
            // ---- fixed-max softmax: LN bounds |S| <= 8, exp directly ----
            #pragma unroll
            for (int nt = 0; nt < 4; nt++) {
                float p0 = __expf(sacc[nt][0]);
                float p1 = __expf(sacc[nt][1]);
                float p2 = __expf(sacc[nt][2]);
                float p3 = __expf(sacc[nt][3]);
                rs0 += p0 + p1; rs1 += p2 + p3;
                sacc[nt][0] = f2tf32(p0); sacc[nt][1] = f2tf32(p1);
                sacc[nt][2] = f2tf32(p2); sacc[nt][3] = f2tf32(p3);
            }
            rs0 += __shfl_xor_sync(0xFFFFFFFFu, rs0, 1);
            rs0 += __shfl_xor_sync(0xFFFFFFFFu, rs0, 2);
            rs1 += __shfl_xor_sync(0xFFFFFFFFu, rs1, 1);
            rs1 += __shfl_xor_sync(0xFFFFFFFFu, rs1, 2);
            l0 += rs0; l1 += rs1;
        }

        // ---- O += P V  (V^T fragments via LDS.64) ----
        #pragma unroll
        for (int kc = 0; kc < 4; kc++) {
            int srcA = qb4 + (tg >> 1);
            int srcB = srcA + 2;
            float v0 = __shfl_sync(0xFFFFFFFFu, sacc[kc][0], srcA);
            float v1 = __shfl_sync(0xFFFFFFFFu, sacc[kc][1], srcA);
            float v2 = __shfl_sync(0xFFFFFFFFu, sacc[kc][0], srcB);
            float v3 = __shfl_sync(0xFFFFFFFFu, sacc[kc][1], srcB);
            float w0 = __shfl_sync(0xFFFFFFFFu, sacc[kc][2], srcA);
            float w1 = __shfl_sync(0xFFFFFFFFu, sacc[kc][3], srcA);
            float w2 = __shfl_sync(0xFFFFFFFFu, sacc[kc][2], srcB);
            float w3 = __shfl_sync(0xFFFFFFFFu, sacc[kc][3], srcB);
            uint32_t a[4];
            bool odd = (tg & 1);
            a[0] = __float_as_uint(odd ? v1 : v0);
            a[1] = __float_as_uint(odd ? w1 : w0);
            a[2] = __float_as_uint(odd ? v3 : v2);
            a[3] = __float_as_uint(odd ? w3 : w2);
            #pragma unroll
            for (int nt = 0; nt < 8; nt++) {
                // V^T row = d (nt*8+group); cols = tokens kc*8 + {tg, tg+4} interleaved -> float2
                float2 vf = *(const float2*)(Vb + (nt * 8 + group) * VPITCH + kc * 8 + tg * 2);
                mma_tf32(oacc[nt], a, __float_as_uint(vf.x), __float_as_uint(vf.y));
            }
        }

        __syncthreads();
        if (t + 2 < NTILES) prefetch(t + 2, buf);
    }

    // ---- finalize ----
    float inv0 = 1.f / l0, inv1 = 1.f / l1;
    int tok0 = qtile * QR + warp * 16 + group;
    float* or0 = aout + ((size_t)(bB * Nv + tok0)) * Cv + h * Dv;
    float* or1 = or0 + 8 * (size_t)Cv;
    #pragma unroll
    for (int nt = 0; nt < 8; nt++) {
        int c = nt * 8 + 2 * tg;
        *(float2*)(or0 + c) = make_float2(oacc[nt][0] * inv0, oacc[nt][1] * inv0);
        *(float2*)(or1 + c) = make_float2(oacc[nt][2] * inv1, oacc[nt][3] * inv1);
    }
}

// ---------------- launch ----------------
extern "C" void kernel_launch(void* const* d_in, const int* in_sizes, int n_in,
                              void* d_out, int out_size)
{
    const float* x            = (const float*)d_in[0];
    const unsigned char* mask = (const unsigned char*)d_in[1];
    const float* w_qkv        = (const float*)d_in[2];
    const float* w_proj       = (const float*)d_in[3];
    const float* b_proj       = (const float*)d_in[4];
    const float* qg           = (const float*)d_in[5];
    const float* qb           = (const float*)d_in[6];
    const float* kg           = (const float*)d_in[7];
    const float* kb           = (const float*)d_in[8];
    float* out                = (float*)d_out;

    void *pq, *pk, *pv, *pa, *pf;
    cudaGetSymbolAddress(&pq, g_q);
    cudaGetSymbolAddress(&pk, g_k);
    cudaGetSymbolAddress(&pv, g_v);
    cudaGetSymbolAddress(&pa, g_attn);
    cudaGetSymbolAddress(&pf, g_maskflag);
    float* q = (float*)pq; float* k = (float*)pk; float* v = (float*)pv;
    float* attn = (float*)pa; int* flag = (int*)pf;

    const int FLASH_SMEM = FLASH_SMEM_F * 4;   // 57344 B -> 4 CTAs/SM
    cudaFuncSetAttribute(flash_kernel<false>, cudaFuncAttributeMaxDynamicSharedMemorySize, FLASH_SMEM);
    cudaFuncSetAttribute(flash_kernel<true>,  cudaFuncAttributeMaxDynamicSharedMemorySize, FLASH_SMEM);

    // 0) mask any-true flag
    cudaMemsetAsync(flag, 0, sizeof(int));
    mask_any_kernel<<<512, 256>>>((const uint4*)mask, (Bv*Nv*Nv)/16, flag);

    // 1) QKV projection
    {
        EpiQKV epi{q, k, v};
        dim3 grid(C3/128, MROWS/128, 1);
        gemm_tc_tn<128,128,32,32,64><<<grid, 256>>>(x, w_qkv, Cv, 0, 0, epi);
    }
    // 2) LayerNorm q, k
    {
        int warps = 2 * BHv * Nv;
        ln_kernel<<<warps/8, 256>>>(q, k, qg, qb, kg, kb);
    }
    // 3) fused attention (one of the two instances self-selects on the flag)
    {
        dim3 grid(Nv/QR, BHv);
        flash_kernel<false><<<grid, 128, FLASH_SMEM>>>(q, k, v, mask, flag, attn);
        flash_kernel<true><<<grid, 128, FLASH_SMEM>>>(q, k, v, mask, flag, attn);
    }
    // 4) out = attn @ w_proj^T + b_proj
    {
        EpiOut epi{out, b_proj};
        dim3 grid(Cv/128, MROWS/128, 1);
        gemm_tc_tn<128,128,32,32,64><<<grid, 256>>>(attn, w_proj, Cv, 0, 0, epi);
    }
}

// round 8
// speedup vs baseline: 1.2804x; 1.0686x over previous
#include <cuda_runtime.h>
#include <math.h>
#include <float.h>
#include <stdint.h>

// Problem constants
#define Bv 2
#define Nv 2048
#define Cv 1024
#define Hv 16
#define Dv 64
#define BHv (Bv*Hv)        // 32
#define MROWS (Bv*Nv)      // 4096
#define C3 (3*Cv)          // 3072

// Static device scratch (allocation-free rule)
__device__ float g_q[BHv*Nv*Dv];            // [b,h,n,d] (d interleaved in 8-blocks)
__device__ float g_k[BHv*Nv*Dv];            // [b,h,n,d] (d interleaved)
__device__ float g_v[BHv*Nv*Dv];            // [b,h,d,n] TRANSPOSED, natural token order
__device__ float g_attn[MROWS*Cv];          // [b*n, h*d]
__device__ int   g_maskflag;

// ---------------- tf32 helpers ----------------
__device__ __forceinline__ float f2tf32(float x) {
    uint32_t u;
    asm("cvt.rna.tf32.f32 %0, %1;" : "=r"(u) : "f"(x));
    return __uint_as_float(u);
}

__device__ __forceinline__ void mma_tf32(float* c, const uint32_t* a, uint32_t b0, uint32_t b1) {
    asm volatile(
        "mma.sync.aligned.m16n8k8.row.col.f32.tf32.tf32.f32 "
        "{%0,%1,%2,%3}, {%4,%5,%6,%7}, {%8,%9}, {%0,%1,%2,%3};\n"
        : "+f"(c[0]), "+f"(c[1]), "+f"(c[2]), "+f"(c[3])
        : "r"(a[0]), "r"(a[1]), "r"(a[2]), "r"(a[3]), "r"(b0), "r"(b1));
}

__device__ __forceinline__ void cp16(uint32_t dst, const void* src) {
    asm volatile("cp.async.cg.shared.global [%0], [%1], 16;\n" :: "r"(dst), "l"(src));
}

// interleave within 8-blocks: orig j -> pos ((j&3)<<1)|(j>>2)
__device__ __forceinline__ int perm8(int j) { return ((j & 3) << 1) | (j >> 2); }
__device__ __forceinline__ int iperm8(int p) { return (p >> 1) | ((p & 1) << 2); }

// ---------------- Epilogue functors ----------------
struct EpiQKV {
    float *q, *k, *v;
    __device__ __forceinline__ void operator()(int bz, int m, int n, float val) const {
        int b   = m >> 11;
        int tok = m & 2047;
        int which = n >> 10;        // 0=q,1=k,2=v
        int h   = (n & 1023) >> 6;
        int dd  = n & 63;
        if (which == 2) {
            // V: transposed [b,h][d][n], NATURAL token order, tf32-rounded
            v[(((b*Hv + h)*Dv + dd) << 11) + tok] = f2tf32(val);
        } else {
            int dp = (dd & ~7) | perm8(dd & 7);   // interleave q/k d-columns
            float* dst = (which == 0) ? q : k;
            dst[(((b*Hv + h)*Nv + tok) << 6) + dp] = val;
        }
    }
};

struct EpiOut {
    float* out;
    const float* bias;
    __device__ __forceinline__ void operator()(int bz, int m, int n, float val) const {
        out[(size_t)m*Cv + n] = val + bias[n];
    }
};

// ============ tf32 tensor-core GEMM, TN: C = A(MxK,rm) * B(NxK,rm)^T ============
template<int BM, int BN, int BK, int WM, int WN, class Epi>
__global__ void __launch_bounds__((BM/WM)*(BN/WN)*32)
gemm_tc_tn(const float* __restrict__ A, const float* __restrict__ B,
           int K, long long sA, long long sB, Epi epi)
{
    constexpr int WARPS_M = BM / WM;
    constexpr int WARPS_N = BN / WN;
    constexpr int THREADS = WARPS_M * WARPS_N * 32;
    constexpr int MT = WM / 16;
    constexpr int NT = WN / 8;
    constexpr int PAD = 4;
    constexpr int VPR = BK / 4;

    __shared__ float As[BM][BK + PAD];
    __shared__ float Bs[BN][BK + PAD];

    const int bz = blockIdx.z;
    A += (long long)bz * sA + (long long)blockIdx.y * BM * K;
    B += (long long)bz * sB + (long long)blockIdx.x * BN * K;
    const int tid  = threadIdx.x;
    const int warp = tid >> 5, lane = tid & 31;
    const int wm = warp / WARPS_N, wn = warp % WARPS_N;
    const int group = lane >> 2, tg = lane & 3;

    float acc[MT][NT][4];
    #pragma unroll
    for (int i = 0; i < MT; i++)
        #pragma unroll
        for (int j = 0; j < NT; j++)
            #pragma unroll
            for (int r = 0; r < 4; r++) acc[i][j][r] = 0.f;

    for (int k0 = 0; k0 < K; k0 += BK) {
        #pragma unroll
        for (int i = tid; i < BM * VPR; i += THREADS) {
            int m = i / VPR, kv = i % VPR;
            float4 t = *(const float4*)(A + (long long)m * K + k0 + kv * 4);
            t.x = f2tf32(t.x); t.y = f2tf32(t.y); t.z = f2tf32(t.z); t.w = f2tf32(t.w);
            *(float4*)&As[m][kv * 4] = t;
        }
        #pragma unroll
        for (int i = tid; i < BN * VPR; i += THREADS) {
            int n = i / VPR, kv = i % VPR;
            float4 t = *(const float4*)(B + (long long)n * K + k0 + kv * 4);
            t.x = f2tf32(t.x); t.y = f2tf32(t.y); t.z = f2tf32(t.z); t.w = f2tf32(t.w);
            *(float4*)&Bs[n][kv * 4] = t;
        }
        __syncthreads();

        #pragma unroll
        for (int kk = 0; kk < BK; kk += 8) {
            uint32_t af[MT][4], bf[NT][2];
            #pragma unroll
            for (int mt = 0; mt < MT; mt++) {
                int r = wm * WM + mt * 16 + group;
                af[mt][0] = __float_as_uint(As[r    ][kk + tg]);
                af[mt][1] = __float_as_uint(As[r + 8][kk + tg]);
                af[mt][2] = __float_as_uint(As[r    ][kk + tg + 4]);
                af[mt][3] = __float_as_uint(As[r + 8][kk + tg + 4]);
            }
            #pragma unroll
            for (int nt = 0; nt < NT; nt++) {
                int c = wn * WN + nt * 8 + group;
                bf[nt][0] = __float_as_uint(Bs[c][kk + tg]);
                bf[nt][1] = __float_as_uint(Bs[c][kk + tg + 4]);
            }
            #pragma unroll
            for (int mt = 0; mt < MT; mt++)
                #pragma unroll
                for (int nt = 0; nt < NT; nt++)
                    mma_tf32(acc[mt][nt], af[mt], bf[nt][0], bf[nt][1]);
        }
        __syncthreads();
    }

    const int bm = blockIdx.y * BM, bn = blockIdx.x * BN;
    #pragma unroll
    for (int mt = 0; mt < MT; mt++)
        #pragma unroll
        for (int nt = 0; nt < NT; nt++) {
            int r0 = bm + wm * WM + mt * 16 + group;
            int c0 = bn + wn * WN + nt * 8 + tg * 2;
            epi(bz, r0,     c0,     acc[mt][nt][0]);
            epi(bz, r0,     c0 + 1, acc[mt][nt][1]);
            epi(bz, r0 + 8, c0,     acc[mt][nt][2]);
            epi(bz, r0 + 8, c0 + 1, acc[mt][nt][3]);
        }
}

// ---------------- LayerNorm over d=64 (interleaved layout), one warp per row ----------------
__global__ void ln_kernel(float* __restrict__ q, float* __restrict__ k,
                          const float* __restrict__ qg, const float* __restrict__ qb,
                          const float* __restrict__ kg, const float* __restrict__ kb)
{
    int warp = (blockIdx.x * blockDim.x + threadIdx.x) >> 5;
    int lane = threadIdx.x & 31;
    const int total = BHv * Nv;
    float* buf; const float *g, *bt;
    int r = warp;
    if (r < total) { buf = q; g = qg; bt = qb; }
    else           { r -= total; buf = k; g = kg; bt = kb; }
    float* p = buf + (size_t)r * Dv;
    int p0 = lane, p1 = lane + 32;
    int o0 = (p0 & ~7) | iperm8(p0 & 7);
    int o1 = (p1 & ~7) | iperm8(p1 & 7);
    float x0 = p[p0], x1 = p[p1];
    float s = x0 + x1;
    #pragma unroll
    for (int o = 16; o; o >>= 1) s += __shfl_xor_sync(0xFFFFFFFFu, s, o);
    float mu = s * (1.f/64.f);
    float d0 = x0 - mu, d1 = x1 - mu;
    float v2 = d0*d0 + d1*d1;
    #pragma unroll
    for (int o = 16; o; o >>= 1) v2 += __shfl_xor_sync(0xFFFFFFFFu, v2, o);
    float inv = rsqrtf(v2 * (1.f/64.f) + 1e-5f);
    p[p0] = f2tf32(d0 * inv * g[o0] + bt[o0]);
    p[p1] = f2tf32(d1 * inv * g[o1] + bt[o1]);
}

// ---------------- mask any-true scan ----------------
__global__ void mask_any_kernel(const uint4* __restrict__ m, int n4, int* flag)
{
    int i = blockIdx.x * blockDim.x + threadIdx.x;
    bool any = false;
    for (; i < n4; i += gridDim.x * blockDim.x) {
        uint4 t = m[i];
        any |= ((t.x | t.y | t.z | t.w) != 0u);
    }
    if (__syncthreads_or(any)) {
        if (threadIdx.x == 0) atomicOr(flag, 1);
    }
}

// ================= fused flash attention =================
// CTA: 128 threads (4 warps, 64 q-rows). KV tile 32 tokens, double-buffered.
// PV uses a kv-relabeling sigma = perm8 so P accumulators feed the mma A operand
// directly ({c0,c2,c1,c3}) with V in natural token order — no shuffles.
#define QR 64
#define KT 32
#define PITCH 72            // Q/K row pitch (floats): conflict-free LDS.64
#define VPITCH 40           // V^T row pitch (floats): conflict-free LDS.64
#define QTILEF (QR*PITCH)   // 4608
#define KTILEF (KT*PITCH)   // 2304
#define VTILEF (Dv*VPITCH)  // 2560
#define OFF_K0 QTILEF
#define OFF_K1 (QTILEF + KTILEF)
#define OFF_V0 (QTILEF + 2*KTILEF)
#define OFF_V1 (QTILEF + 2*KTILEF + VTILEF)
#define FLASH_SMEM_F (QTILEF + 2*KTILEF + 2*VTILEF)   // 14336 floats = 57344 B

template<bool MASKED>
__global__ void __launch_bounds__(128, 4)
flash_kernel(const float* __restrict__ q, const float* __restrict__ k,
             const float* __restrict__ v, const unsigned char* __restrict__ mask,
             const int* __restrict__ maskflag, float* __restrict__ aout)
{
    const int mf = *maskflag;
    if (MASKED ? (mf == 0) : (mf != 0)) return;   // exactly one instance runs

    extern __shared__ float sm[];
    const int tid  = threadIdx.x;
    const int warp = tid >> 5, lane = tid & 31;
    const int group = lane >> 2, tg = lane & 3;
    const int qtile = blockIdx.x;
    const int bh = blockIdx.y;
    const int bB = bh >> 4, h = bh & 15;

    const float* qbase = q + (size_t)bh * Nv * Dv + (size_t)qtile * QR * Dv;
    const float* kbase = k + (size_t)bh * Nv * Dv;
    const float* vbase = v + (size_t)bh * Nv * Dv;      // [d][n] layout
    uint32_t sbase = (uint32_t)__cvta_generic_to_shared(sm);

    // ---- stage Q tile (pre-scaled by d^-1/2) ----
    #pragma unroll
    for (int i = 0; i < 8; i++) {
        int idx = tid + i * 128;              // 64 rows x 16 float4
        int row = idx >> 4, c4 = (idx & 15) * 4;
        float4 t = *(const float4*)(qbase + row * Dv + c4);
        t.x *= 0.125f; t.y *= 0.125f; t.z *= 0.125f; t.w *= 0.125f;
        *(float4*)(sm + row * PITCH + c4) = t;
    }
    __syncthreads();

    auto prefetch = [&](int t, int b) {
        const float* kb = kbase + (size_t)t * KT * Dv;
        const float* vb = vbase + (size_t)t * KT;       // column block of V^T
        uint32_t kd = sbase + (uint32_t)((b ? OFF_K1 : OFF_K0)) * 4u;
        uint32_t vd = sbase + (uint32_t)((b ? OFF_V1 : OFF_V0)) * 4u;
        #pragma unroll
        for (int i = 0; i < 4; i++) {
            int idx = tid + i * 128;
            {   // K: 32 rows x 16 float4
                int row = idx >> 4, c4 = (idx & 15) * 4;
                cp16(kd + (row * PITCH + c4) * 4, kb + row * Dv + c4);
            }
            {   // V^T: 64 rows x 8 float4
                int row = idx >> 3, c4 = (idx & 7) * 4;
                cp16(vd + (row * VPITCH + c4) * 4, vb + (size_t)row * Nv + c4);
            }
        }
        asm volatile("cp.async.commit_group;\n" ::: "memory");
    };

    prefetch(0, 0);
    prefetch(1, 1);

    // ---- running state ----
    float m0 = -FLT_MAX, m1 = -FLT_MAX, l0 = 0.f, l1 = 0.f;
    float oacc[8][4];
    #pragma unroll
    for (int i = 0; i < 8; i++)
        #pragma unroll
        for (int j = 0; j < 4; j++) oacc[i][j] = 0.f;

    const int NTILES = Nv / KT;               // 64
    const float* Qr0 = sm + (warp * 16 + group) * PITCH + tg * 2;
    const float* Qr1 = Qr0 + 8 * PITCH;

    for (int t = 0; t < NTILES; t++) {
        const int buf = t & 1;
        if (t < NTILES - 1) asm volatile("cp.async.wait_group 1;\n" ::: "memory");
        else                asm volatile("cp.async.wait_group 0;\n" ::: "memory");
        __syncthreads();

        const float* Kb = sm + (buf ? OFF_K1 : OFF_K0);
        const float* Vb = sm + (buf ? OFF_V1 : OFF_V0);

        // ---- S = Q K^T (16 x 32 per warp), LDS.64 fragments ----
        float sacc[4][4];
        #pragma unroll
        for (int nt = 0; nt < 4; nt++)
            #pragma unroll
            for (int r = 0; r < 4; r++) sacc[nt][r] = 0.f;

        #pragma unroll
        for (int kk = 0; kk < 8; kk++) {
            float2 qa = *(const float2*)(Qr0 + kk * 8);
            float2 qb = *(const float2*)(Qr1 + kk * 8);
            uint32_t a[4] = { __float_as_uint(qa.x), __float_as_uint(qb.x),
                              __float_as_uint(qa.y), __float_as_uint(qb.y) };
            #pragma unroll
            for (int nt = 0; nt < 4; nt++) {
                float2 kf = *(const float2*)(Kb + (nt * 8 + group) * PITCH + kk * 8 + tg * 2);
                mma_tf32(sacc[nt], a, __float_as_uint(kf.x), __float_as_uint(kf.y));
            }
        }

        float rs0 = 0.f, rs1 = 0.f;
        if (MASKED) {
            // ---- mask + full online softmax (general path) ----
            const unsigned char* mr0 = mask + ((size_t)(bB * Nv + qtile*QR + warp*16 + group)) * Nv + t * KT;
            const unsigned char* mr1 = mr0 + 8 * Nv;
            #pragma unroll
            for (int nt = 0; nt < 4; nt++) {
                int c = nt * 8 + 2 * tg;
                if (mr0[c])     sacc[nt][0] = -FLT_MAX;
                if (mr0[c + 1]) sacc[nt][1] = -FLT_MAX;
                if (mr1[c])     sacc[nt][2] = -FLT_MAX;
                if (mr1[c + 1]) sacc[nt][3] = -FLT_MAX;
            }
            float mn0 = -FLT_MAX, mn1 = -FLT_MAX;
            #pragma unroll
            for (int nt = 0; nt < 4; nt++) {
                mn0 = fmaxf(mn0, fmaxf(sacc[nt][0], sacc[nt][1]));
                mn1 = fmaxf(mn1, fmaxf(sacc[nt][2], sacc[nt][3]));
            }
            mn0 = fmaxf(mn0, __shfl_xor_sync(0xFFFFFFFFu, mn0, 1));
            mn0 = fmaxf(mn0, __shfl_xor_sync(0xFFFFFFFFu, mn0, 2));
            mn1 = fmaxf(mn1, __shfl_xor_sync(0xFFFFFFFFu, mn1, 1));
            mn1 = fmaxf(mn1, __shfl_xor_sync(0xFFFFFFFFu, mn1, 2));
            float mt0 = fmaxf(m0, mn0), mt1 = fmaxf(m1, mn1);
            #pragma unroll
            for (int nt = 0; nt < 4; nt++) {
                float p0 = __expf(sacc[nt][0] - mt0);
                float p1 = __expf(sacc[nt][1] - mt0);
                float p2 = __expf(sacc[nt][2] - mt1);
                float p3 = __expf(sacc[nt][3] - mt1);
                rs0 += p0 + p1; rs1 += p2 + p3;
                sacc[nt][0] = f2tf32(p0); sacc[nt][1] = f2tf32(p1);
                sacc[nt][2] = f2tf32(p2); sacc[nt][3] = f2tf32(p3);
            }
            rs0 += __shfl_xor_sync(0xFFFFFFFFu, rs0, 1);
            rs0 += __shfl_xor_sync(0xFFFFFFFFu, rs0, 2);
            rs1 += __shfl_xor_sync(0xFFFFFFFFu, rs1, 1);
            rs1 += __shfl_xor_sync(0xFFFFFFFFu, rs1, 2);
            if (__any_sync(0xFFFFFFFFu, (mn0 > m0) | (mn1 > m1))) {
                float a0 = __expf(m0 - mt0), a1 = __expf(m1 - mt1);
                l0 = a0 * l0 + rs0;
                l1 = a1 * l1 + rs1;
                #pragma unroll
                for (int i = 0; i < 8; i++) {
                    oacc[i][0] *= a0; oacc[i][1] *= a0;
                    oacc[i][2] *= a1; oacc[i][3] *= a1;
                }
            } else {
                l0 += rs0; l1 += rs1;
            }
            m0 = mt0; m1 = mt1;
        } else {
            // ---- fixed-max softmax: LN bounds |S| <= 8, exp directly ----
            #pragma unroll
            for (int nt = 0; nt < 4; nt++) {
                float p0 = __expf(sacc[nt][0]);
                float p1 = __expf(sacc[nt][1]);
                float p2 = __expf(sacc[nt][2]);
                float p3 = __expf(sacc[nt][3]);
                rs0 += p0 + p1; rs1 += p2 + p3;
                sacc[nt][0] = f2tf32(p0); sacc[nt][1] = f2tf32(p1);
                sacc[nt][2] = f2tf32(p2); sacc[nt][3] = f2tf32(p3);
            }
            rs0 += __shfl_xor_sync(0xFFFFFFFFu, rs0, 1);
            rs0 += __shfl_xor_sync(0xFFFFFFFFu, rs0, 2);
            rs1 += __shfl_xor_sync(0xFFFFFFFFu, rs1, 1);
            rs1 += __shfl_xor_sync(0xFFFFFFFFu, rs1, 2);
            l0 += rs0; l1 += rs1;
        }

        // ---- O += P V : P accumulators feed A directly (kv relabeled by perm8) ----
        #pragma unroll
        for (int kc = 0; kc < 4; kc++) {
            uint32_t a[4] = { __float_as_uint(sacc[kc][0]),
                              __float_as_uint(sacc[kc][2]),
                              __float_as_uint(sacc[kc][1]),
                              __float_as_uint(sacc[kc][3]) };
            #pragma unroll
            for (int nt = 0; nt < 8; nt++) {
                // V^T row = d (nt*8+group); cols = tokens kc*8 + {2tg, 2tg+1} (natural order)
                float2 vf = *(const float2*)(Vb + (nt * 8 + group) * VPITCH + kc * 8 + tg * 2);
                mma_tf32(oacc[nt], a, __float_as_uint(vf.x), __float_as_uint(vf.y));
            }
        }

        __syncthreads();
        if (t + 2 < NTILES) prefetch(t + 2, buf);
    }

    // ---- finalize ----
    float inv0 = 1.f / l0, inv1 = 1.f / l1;
    int tok0 = qtile * QR + warp * 16 + group;
    float* or0 = aout + ((size_t)(bB * Nv + tok0)) * Cv + h * Dv;
    float* or1 = or0 + 8 * (size_t)Cv;
    #pragma unroll
    for (int nt = 0; nt < 8; nt++) {
        int c = nt * 8 + 2 * tg;
        *(float2*)(or0 + c) = make_float2(oacc[nt][0] * inv0, oacc[nt][1] * inv0);
        *(float2*)(or1 + c) = make_float2(oacc[nt][2] * inv1, oacc[nt][3] * inv1);
    }
}

// ---------------- launch ----------------
extern "C" void kernel_launch(void* const* d_in, const int* in_sizes, int n_in,
                              void* d_out, int out_size)
{
    const float* x            = (const float*)d_in[0];
    const unsigned char* mask = (const unsigned char*)d_in[1];
    const float* w_qkv        = (const float*)d_in[2];
    const float* w_proj       = (const float*)d_in[3];
    const float* b_proj       = (const float*)d_in[4];
    const float* qg           = (const float*)d_in[5];
    const float* qb           = (const float*)d_in[6];
    const float* kg           = (const float*)d_in[7];
    const float* kb           = (const float*)d_in[8];
    float* out                = (float*)d_out;

    void *pq, *pk, *pv, *pa, *pf;
    cudaGetSymbolAddress(&pq, g_q);
    cudaGetSymbolAddress(&pk, g_k);
    cudaGetSymbolAddress(&pv, g_v);
    cudaGetSymbolAddress(&pa, g_attn);
    cudaGetSymbolAddress(&pf, g_maskflag);
    float* q = (float*)pq; float* k = (float*)pk; float* v = (float*)pv;
    float* attn = (float*)pa; int* flag = (int*)pf;

    const int FLASH_SMEM = FLASH_SMEM_F * 4;   // 57344 B -> 4 CTAs/SM
    cudaFuncSetAttribute(flash_kernel<false>, cudaFuncAttributeMaxDynamicSharedMemorySize, FLASH_SMEM);
    cudaFuncSetAttribute(flash_kernel<true>,  cudaFuncAttributeMaxDynamicSharedMemorySize, FLASH_SMEM);

    // 0) mask any-true flag
    cudaMemsetAsync(flag, 0, sizeof(int));
    mask_any_kernel<<<512, 256>>>((const uint4*)mask, (Bv*Nv*Nv)/16, flag);

    // 1) QKV projection
    {
        EpiQKV epi{q, k, v};
        dim3 grid(C3/128, MROWS/128, 1);
        gemm_tc_tn<128,128,32,32,64><<<grid, 256>>>(x, w_qkv, Cv, 0, 0, epi);
    }
    // 2) LayerNorm q, k
    {
        int warps = 2 * BHv * Nv;
        ln_kernel<<<warps/8, 256>>>(q, k, qg, qb, kg, kb);
    }
    // 3) fused attention (one of the two instances self-selects on the flag)
    {
        dim3 grid(Nv/QR, BHv);
        flash_kernel<false><<<grid, 128, FLASH_SMEM>>>(q, k, v, mask, flag, attn);
        flash_kernel<true><<<grid, 128, FLASH_SMEM>>>(q, k, v, mask, flag, attn);
    }
    // 4) out = attn @ w_proj^T + b_proj
    {
        EpiOut epi{out, b_proj};
        dim3 grid(Cv/128, MROWS/128, 1);
        gemm_tc_tn<128,128,32,32,64><<<grid, 256>>>(attn, w_proj, Cv, 0, 0, epi);
    }
}